// round 6
// baseline (speedup 1.0000x reference)
#include <cuda_runtime.h>

#define NT 8192
#define ND 2048
#define NE 16
#define CAP 512
#define FULLM 0xFFFFFFFFu
#define CINF 0x7FFFFFFF

typedef unsigned long long u64;

__device__ float g_probs[NT * NE];   // softmax probs per token
__device__ u64   g_prefs[NT];        // packed expert-preference order (16 nibbles)

__device__ __forceinline__ u64 ffma2(u64 a, u64 b, u64 c) {
    u64 d;
    asm("fma.rn.f32x2 %0, %1, %2, %3;" : "=l"(d) : "l"(a), "l"(b), "l"(c));
    return d;
}

// =====================================================================
// Kernel 1: GEMV + softmax + preference packing (unchanged)
// =====================================================================
__global__ void __launch_bounds__(128) gemv_kernel(const float* __restrict__ f,
                                                   const float* __restrict__ W,
                                                   const float* __restrict__ b) {
    const int lane = threadIdx.x & 31;
    const int wid  = threadIdx.x >> 5;
    const int t0   = (blockIdx.x * 4 + wid) * 4;

    const ulonglong2* F  = reinterpret_cast<const ulonglong2*>(f + (size_t)t0 * ND);
    const ulonglong2* Wv = reinterpret_cast<const ulonglong2*>(W);

    u64 acc[4][NE];
#pragma unroll
    for (int t = 0; t < 4; ++t)
#pragma unroll
        for (int e = 0; e < NE; ++e) acc[t][e] = 0ull;

#pragma unroll 2
    for (int i = 0; i < 16; ++i) {
        const int k = i * 32 + lane;
        const ulonglong2 a0 = F[k];
        const ulonglong2 a1 = F[k + 512];
        const ulonglong2 a2 = F[k + 1024];
        const ulonglong2 a3 = F[k + 1536];
#pragma unroll
        for (int e = 0; e < NE; ++e) {
            const ulonglong2 w = Wv[e * 512 + k];
            acc[0][e] = ffma2(a0.x, w.x, acc[0][e]);
            acc[0][e] = ffma2(a0.y, w.y, acc[0][e]);
            acc[1][e] = ffma2(a1.x, w.x, acc[1][e]);
            acc[1][e] = ffma2(a1.y, w.y, acc[1][e]);
            acc[2][e] = ffma2(a2.x, w.x, acc[2][e]);
            acc[2][e] = ffma2(a2.y, w.y, acc[2][e]);
            acc[3][e] = ffma2(a3.x, w.x, acc[3][e]);
            acc[3][e] = ffma2(a3.y, w.y, acc[3][e]);
        }
    }

    float aff[NE];
#pragma unroll
    for (int t = 0; t < 4; ++t) {
#pragma unroll
        for (int e = 0; e < NE; ++e) {
            float sv = __uint_as_float((unsigned)acc[t][e]) +
                       __uint_as_float((unsigned)(acc[t][e] >> 32));
#pragma unroll
            for (int o = 16; o; o >>= 1) sv += __shfl_xor_sync(FULLM, sv, o);
            if (lane == t) aff[e] = sv;
        }
    }

    if (lane < 4) {
        const int t = t0 + lane;
#pragma unroll
        for (int e = 0; e < NE; ++e) aff[e] += __ldg(b + e);

        float m = aff[0];
#pragma unroll
        for (int e = 1; e < NE; ++e) m = fmaxf(m, aff[e]);
        float p[NE]; float s = 0.f;
#pragma unroll
        for (int e = 0; e < NE; ++e) { p[e] = expf(aff[e] - m); s += p[e]; }
        const float inv = 1.f / s;
#pragma unroll
        for (int e = 0; e < NE; ++e) g_probs[t * NE + e] = p[e] * inv;

        u64 key[NE];
#pragma unroll
        for (int e = 0; e < NE; ++e) {
            unsigned u = __float_as_uint(aff[e]);
            u = (u & 0x80000000u) ? ~u : (u | 0x80000000u);
            key[e] = (1ull << 40) | ((u64)u << 4) | (u64)(NE - 1 - e);
        }
        unsigned used = 0;
        u64 pref = 0;
#pragma unroll
        for (int i = 0; i < NE; ++i) {
            int best = 0; u64 bk = 0;
#pragma unroll
            for (int e = 0; e < NE; ++e) {
                const bool take = !((used >> e) & 1u) && key[e] > bk;
                bk   = take ? key[e] : bk;
                best = take ? e : best;
            }
            used |= 1u << best;
            pref |= ((u64)best) << (4 * i);
        }
        g_prefs[t] = pref;
    }
}

// =====================================================================
// Kernel 2: phased balanced assignment v5.
// word-based live-region updates, 2 barriers/phase, atomic-free build.
// =====================================================================
#define S_PREF_OFF 0
#define S_CH_OFF   65536
#define S_BLK_OFF  73728
#define S_W_OFF    75776
#define S_INT_OFF  76800
#define SMEM_BYTES 76928
// s_int: [0..15] need, [16] active, [17] start, [18] cut slot A, [19] cut slot B

__global__ void __launch_bounds__(1024) assign_kernel(float* __restrict__ out) {
    extern __shared__ unsigned char smem[];
    u64*      s_pref = (u64*)(smem + S_PREF_OFF);
    unsigned* s_ch   = (unsigned*)(smem + S_CH_OFF);   // 2048 words
    int*      s_blk  = (int*)(smem + S_BLK_OFF);       // [16][32]
    u64 (*s_w)[4]    = (u64(*)[4])(smem + S_W_OFF);
    int*      s_int  = (int*)(smem + S_INT_OFF);

    const int tid  = threadIdx.x;
    const int lane = tid & 31;
    const int wid  = tid >> 5;
    const unsigned ltm = (1u << lane) - 1u;

    for (int i = tid; i < NT; i += 1024) s_pref[i] = g_prefs[i];
    if (tid < NE) s_int[tid] = CAP;
    if (tid == 0) { s_int[16] = 0xFFFF; s_int[17] = 0; s_int[18] = CINF; s_int[19] = CINF; }
    __syncthreads();

    // ---- build: warp wid counts+writes its block (atomic-free) ----
    {
        u64 c0 = 0, c1 = 0, c2 = 0, c3 = 0;
#pragma unroll
        for (int i = 0; i < 2; ++i) {
            const int w = wid * 64 + i * 32 + lane;
            unsigned word = 0;
#pragma unroll
            for (int bb = 0; bb < 4; ++bb) {
                const int c = (int)(s_pref[w * 4 + bb] & 15);
                word |= (unsigned)c << (bb * 8);
                const u64 inc = 1ull << ((c & 3) << 4);
                if      ((c >> 2) == 0) c0 += inc;
                else if ((c >> 2) == 1) c1 += inc;
                else if ((c >> 2) == 2) c2 += inc;
                else                    c3 += inc;
            }
            s_ch[w] = word;
        }
#pragma unroll
        for (int o = 16; o; o >>= 1) {
            c0 += __shfl_xor_sync(FULLM, c0, o);
            c1 += __shfl_xor_sync(FULLM, c1, o);
            c2 += __shfl_xor_sync(FULLM, c2, o);
            c3 += __shfl_xor_sync(FULLM, c3, o);
        }
        if (lane < NE) {
            const u64 sel = (lane >> 2) == 0 ? c0 : (lane >> 2) == 1 ? c1
                          : (lane >> 2) == 2 ? c2 : c3;
            s_blk[lane * 32 + wid] = (int)((sel >> ((lane & 3) << 4)) & 0xFFFF);
        }
    }
    __syncthreads();

    // ---------------- phase loop: 2 barriers per phase ----------------
    for (int phase = 0; phase < NE; ++phase) {
        const int s = s_int[17];
        if (s >= NT) break;
        const int active  = s_int[16];
        const int cutslot = 18 + (phase & 1);

        // ---- step 2: warp e finds expert e's saturation position ----
        if (wid < NE && ((active >> wid) & 1)) {
            const int e = wid;
            const unsigned splat = (unsigned)e * 0x01010101u;
            const int need = s_int[e];
            const int pb   = s >> 8;
            const int ws   = s >> 2;
            const int we_  = (pb + 1) * 64;
            const unsigned mfirst = 0xFFFFFFFFu << ((s & 3) * 8);

            const int i0 = ws + lane * 2;
            unsigned cm0 = 0, cm1 = 0;
            if (i0 < we_) {
                cm0 = __vcmpeq4(s_ch[i0], splat);
                if (i0 == ws) cm0 &= mfirst;
            }
            if (i0 + 1 < we_) cm1 = __vcmpeq4(s_ch[i0 + 1], splat);
            const int lcnt = (__popc(cm0) + __popc(cm1)) >> 3;
            int linc = lcnt;
#pragma unroll
            for (int o = 1; o < 32; o <<= 1) {
                const int u = __shfl_up_sync(FULLM, linc, o);
                if (lane >= o) linc += u;
            }
            const int ptotal = __shfl_sync(FULLM, linc, 31);

            const int bval = (lane > pb) ? s_blk[e * 32 + lane] : 0;
            int binc = bval;
#pragma unroll
            for (int o = 1; o < 32; o <<= 1) {
                const int u = __shfl_up_sync(FULLM, binc, o);
                if (lane >= o) binc += u;
            }
            const int btotal = __shfl_sync(FULLM, binc, 31);

            if (ptotal + btotal >= need) {
                if (ptotal >= need) {
                    const unsigned bal = __ballot_sync(FULLM, linc >= need);
                    const int cl = __ffs(bal) - 1;
                    if (lane == cl) {
                        int rem = need - (linc - lcnt);
                        int pos = -1;
#pragma unroll
                        for (int bb = 0; bb < 4 && pos < 0; ++bb)
                            if ((cm0 >> (bb * 8)) & 1u && --rem == 0) pos = i0 * 4 + bb;
#pragma unroll
                        for (int bb = 0; bb < 4 && pos < 0; ++bb)
                            if ((cm1 >> (bb * 8)) & 1u && --rem == 0) pos = (i0 + 1) * 4 + bb;
                        atomicMin(&s_int[cutslot], (pos << 4) | e);
                    }
                } else {
                    const int rem2 = need - ptotal;
                    const unsigned bal = __ballot_sync(FULLM, binc >= rem2);
                    const int kc   = __ffs(bal) - 1;
                    const int excl = __shfl_sync(FULLM, binc - bval, kc);
                    const int rem3 = rem2 - excl;
                    const int j0 = kc * 64 + lane * 2;
                    const unsigned d0 = __vcmpeq4(s_ch[j0], splat);
                    const unsigned d1 = __vcmpeq4(s_ch[j0 + 1], splat);
                    const int lc = (__popc(d0) + __popc(d1)) >> 3;
                    int li = lc;
#pragma unroll
                    for (int o = 1; o < 32; o <<= 1) {
                        const int u = __shfl_up_sync(FULLM, li, o);
                        if (lane >= o) li += u;
                    }
                    const unsigned bal2 = __ballot_sync(FULLM, li >= rem3);
                    const int cl2 = __ffs(bal2) - 1;
                    if (lane == cl2) {
                        int rem = rem3 - (li - lc);
                        int pos = -1;
#pragma unroll
                        for (int bb = 0; bb < 4 && pos < 0; ++bb)
                            if ((d0 >> (bb * 8)) & 1u && --rem == 0) pos = j0 * 4 + bb;
#pragma unroll
                        for (int bb = 0; bb < 4 && pos < 0; ++bb)
                            if ((d1 >> (bb * 8)) & 1u && --rem == 0) pos = (j0 + 1) * 4 + bb;
                        atomicMin(&s_int[cutslot], (pos << 4) | e);
                    }
                }
            }
        }
        __syncthreads();                               // B1: cut final

        const int mv = s_int[cutslot];
        if (mv == CINF) {                              // safety; unreachable
            if (tid == 0) s_int[17] = NT;
            __syncthreads();
            continue;
        }
        const int pstar = mv >> 4, es = mv & 15;
        const int nactive = active & ~(1 << es);

        // ---- step 3 ∥ state update ∥ step 1 (disjoint work) ----
        if (wid < NE && ((active >> wid) & 1)) {       // need update
            const int e = wid;
            const unsigned splat = (unsigned)e * 0x01010101u;
            const int w0 = s >> 2, w1 = pstar >> 2;
            const unsigned m0 = 0xFFFFFFFFu << ((s & 3) * 8);
            const unsigned m1 = 0xFFFFFFFFu >> ((3 - (pstar & 3)) * 8);
            int cnt = 0;
            for (int w = w0 + lane; w <= w1; w += 32) {
                unsigned cm = __vcmpeq4(s_ch[w], splat);
                if (w == w0) cm &= m0;
                if (w == w1) cm &= m1;
                cnt += __popc(cm) >> 3;
            }
#pragma unroll
            for (int o = 16; o; o >>= 1) cnt += __shfl_xor_sync(FULLM, cnt, o);
            if (lane == 0) s_int[e] -= cnt;
        }
        if (tid == 0) {                                // state update
            s_int[16] = nactive;
            s_int[17] = pstar + 1;
            s_int[cutslot] = CINF;
        }
        {                                              // choice rewrite for es
            const int sn = pstar + 1;
            const int ws = sn >> 2;
            const unsigned splat = (unsigned)es * 0x01010101u;
            const unsigned mfirst = 0xFFFFFFFFu << ((sn & 3) * 8);
            for (int w = ws + tid; w < 2048; w += 1024) {
                unsigned word = s_ch[w];
                unsigned m = __vcmpeq4(word, splat);
                if (w == ws) m &= mfirst;
                if (m) {
                    const int blk = w >> 6;
                    int moved = 0;
                    do {
                        const int bb = (__ffs(m) - 1) >> 3;
                        m &= ~(0xFFu << (bb * 8));
                        u64 p = s_pref[w * 4 + bb];
                        int c = (int)(p & 15);
                        while (!((nactive >> c) & 1)) { p >>= 4; c = (int)(p & 15); }
                        word = (word & ~(0xFFu << (bb * 8))) | ((unsigned)c << (bb * 8));
                        atomicAdd(&s_blk[c * 32 + blk], 1);
                        ++moved;
                    } while (m);
                    atomicAdd(&s_blk[es * 32 + blk], -moved);
                    s_ch[w] = word;
                }
            }
        }
        __syncthreads();                               // B2: phase done
    }

    // ---------------- stable counting sort + gather ----------------
    {
        const int base = wid * 256;
        int myE[8];
#pragma unroll
        for (int j = 0; j < 8; ++j) {
            const int t = base + j * 32 + lane;
            myE[j] = (int)((s_ch[t >> 2] >> ((t & 3) * 8)) & 0xFFu);
        }

        u64 c0 = 0, c1 = 0, c2 = 0, c3 = 0;
#pragma unroll
        for (int j = 0; j < 8; ++j) {
            const int c = myE[j];
            const u64 inc = 1ull << ((c & 3) << 4);
            if      ((c >> 2) == 0) c0 += inc;
            else if ((c >> 2) == 1) c1 += inc;
            else if ((c >> 2) == 2) c2 += inc;
            else                    c3 += inc;
        }
#pragma unroll
        for (int o = 16; o; o >>= 1) {
            c0 += __shfl_xor_sync(FULLM, c0, o);
            c1 += __shfl_xor_sync(FULLM, c1, o);
            c2 += __shfl_xor_sync(FULLM, c2, o);
            c3 += __shfl_xor_sync(FULLM, c3, o);
        }
        if (lane == 0) { s_w[wid][0] = c0; s_w[wid][1] = c1; s_w[wid][2] = c2; s_w[wid][3] = c3; }
        __syncthreads();
        if (wid == 0) {
            u64 v0 = s_w[lane][0], v1 = s_w[lane][1], v2 = s_w[lane][2], v3 = s_w[lane][3];
            u64 i0 = v0, i1 = v1, i2 = v2, i3 = v3;
#pragma unroll
            for (int o = 1; o < 32; o <<= 1) {
                u64 u0 = __shfl_up_sync(FULLM, i0, o), u1 = __shfl_up_sync(FULLM, i1, o);
                u64 u2 = __shfl_up_sync(FULLM, i2, o), u3 = __shfl_up_sync(FULLM, i3, o);
                if (lane >= o) { i0 += u0; i1 += u1; i2 += u2; i3 += u3; }
            }
            s_w[lane][0] = i0 - v0; s_w[lane][1] = i1 - v1;
            s_w[lane][2] = i2 - v2; s_w[lane][3] = i3 - v3;
        }
        __syncthreads();
        const u64 p0 = s_w[wid][0], p1 = s_w[wid][1], p2 = s_w[wid][2], p3 = s_w[wid][3];

        u64 r0 = 0, r1 = 0, r2 = 0, r3 = 0;
#pragma unroll
        for (int j = 0; j < 8; ++j) {
            const int e0 = myE[j];
            int rank = 0;
#pragma unroll
            for (int e = 0; e < NE; ++e) {
                const unsigned bal = __ballot_sync(FULLM, e0 == e);
                if (e0 == e) {
                    const u64 pw = (e >> 2) == 0 ? p0 : (e >> 2) == 1 ? p1
                                 : (e >> 2) == 2 ? p2 : p3;
                    const u64 rw = (e >> 2) == 0 ? r0 : (e >> 2) == 1 ? r1
                                 : (e >> 2) == 2 ? r2 : r3;
                    rank = (int)((pw >> ((e & 3) << 4)) & 0xFFFF)
                         + (int)((rw >> ((e & 3) << 4)) & 0xFFFF)
                         + __popc(bal & ltm);
                }
                const u64 inc = (u64)__popc(bal) << ((e & 3) << 4);
                if      ((e >> 2) == 0) r0 += inc;
                else if ((e >> 2) == 1) r1 += inc;
                else if ((e >> 2) == 2) r2 += inc;
                else                    r3 += inc;
            }
            const int t = base + j * 32 + lane;
            out[e0 * CAP + rank] = (float)t;
            out[NT + t] = g_probs[t * NE + e0];
        }
    }
}

// =====================================================================
extern "C" void kernel_launch(void* const* d_in, const int* in_sizes, int n_in,
                              void* d_out, int out_size) {
    const float* f = (const float*)d_in[0];   // features [8192, 2048] f32
    const float* W = (const float*)d_in[1];   // gate weight [16, 2048] f32
    const float* b = (const float*)d_in[2];   // bias [16] f32
    float* out = (float*)d_out;               // [8192] sort_by_expert ++ [8192] gathered

    gemv_kernel<<<NT / 16, 128>>>(f, W, b);

    cudaFuncSetAttribute(assign_kernel,
                         cudaFuncAttributeMaxDynamicSharedMemorySize, SMEM_BYTES);
    assign_kernel<<<1, 1024, SMEM_BYTES>>>(out);
}

// round 7
// speedup vs baseline: 1.1684x; 1.1684x over previous
#include <cuda_runtime.h>

#define NT 8192
#define ND 2048
#define NE 16
#define CAP 512
#define FULLM 0xFFFFFFFFu
#define CINF 0x7FFFFFFF

typedef unsigned long long u64;

__device__ float g_probsT[NE * NT];  // softmax probs, transposed [e][t]
__device__ u64   g_prefs[NT];        // packed expert-preference order (16 nibbles)

__device__ __forceinline__ u64 ffma2(u64 a, u64 b, u64 c) {
    u64 d;
    asm("fma.rn.f32x2 %0, %1, %2, %3;" : "=l"(d) : "l"(a), "l"(b), "l"(c));
    return d;
}

// =====================================================================
// Kernel 1: GEMV + softmax + preference packing
// =====================================================================
__global__ void __launch_bounds__(128) gemv_kernel(const float* __restrict__ f,
                                                   const float* __restrict__ W,
                                                   const float* __restrict__ b) {
    const int lane = threadIdx.x & 31;
    const int wid  = threadIdx.x >> 5;
    const int t0   = (blockIdx.x * 4 + wid) * 4;

    const ulonglong2* F  = reinterpret_cast<const ulonglong2*>(f + (size_t)t0 * ND);
    const ulonglong2* Wv = reinterpret_cast<const ulonglong2*>(W);

    u64 acc[4][NE];
#pragma unroll
    for (int t = 0; t < 4; ++t)
#pragma unroll
        for (int e = 0; e < NE; ++e) acc[t][e] = 0ull;

#pragma unroll 2
    for (int i = 0; i < 16; ++i) {
        const int k = i * 32 + lane;
        const ulonglong2 a0 = F[k];
        const ulonglong2 a1 = F[k + 512];
        const ulonglong2 a2 = F[k + 1024];
        const ulonglong2 a3 = F[k + 1536];
#pragma unroll
        for (int e = 0; e < NE; ++e) {
            const ulonglong2 w = Wv[e * 512 + k];
            acc[0][e] = ffma2(a0.x, w.x, acc[0][e]);
            acc[0][e] = ffma2(a0.y, w.y, acc[0][e]);
            acc[1][e] = ffma2(a1.x, w.x, acc[1][e]);
            acc[1][e] = ffma2(a1.y, w.y, acc[1][e]);
            acc[2][e] = ffma2(a2.x, w.x, acc[2][e]);
            acc[2][e] = ffma2(a2.y, w.y, acc[2][e]);
            acc[3][e] = ffma2(a3.x, w.x, acc[3][e]);
            acc[3][e] = ffma2(a3.y, w.y, acc[3][e]);
        }
    }

    float aff[NE];
#pragma unroll
    for (int t = 0; t < 4; ++t) {
#pragma unroll
        for (int e = 0; e < NE; ++e) {
            float sv = __uint_as_float((unsigned)acc[t][e]) +
                       __uint_as_float((unsigned)(acc[t][e] >> 32));
#pragma unroll
            for (int o = 16; o; o >>= 1) sv += __shfl_xor_sync(FULLM, sv, o);
            if (lane == t) aff[e] = sv;
        }
    }

    if (lane < 4) {
        const int t = t0 + lane;
#pragma unroll
        for (int e = 0; e < NE; ++e) aff[e] += __ldg(b + e);

        float m = aff[0];
#pragma unroll
        for (int e = 1; e < NE; ++e) m = fmaxf(m, aff[e]);
        float p[NE]; float s = 0.f;
#pragma unroll
        for (int e = 0; e < NE; ++e) { p[e] = expf(aff[e] - m); s += p[e]; }
        const float inv = 1.f / s;
#pragma unroll
        for (int e = 0; e < NE; ++e) g_probsT[e * NT + t] = p[e] * inv;

        u64 key[NE];
#pragma unroll
        for (int e = 0; e < NE; ++e) {
            unsigned u = __float_as_uint(aff[e]);
            u = (u & 0x80000000u) ? ~u : (u | 0x80000000u);
            key[e] = (1ull << 40) | ((u64)u << 4) | (u64)(NE - 1 - e);
        }
        unsigned used = 0;
        u64 pref = 0;
#pragma unroll
        for (int i = 0; i < NE; ++i) {
            int best = 0; u64 bk = 0;
#pragma unroll
            for (int e = 0; e < NE; ++e) {
                const bool take = !((used >> e) & 1u) && key[e] > bk;
                bk   = take ? key[e] : bk;
                best = take ? e : best;
            }
            used |= 1u << best;
            pref |= ((u64)best) << (4 * i);
        }
        g_prefs[t] = pref;
    }
}

// =====================================================================
// Kernel 2: phased balanced assignment v6.
// step3 folded into step2 (need derived from block-count totals);
// match_any + smem-atomic epilogue.
// =====================================================================
#define S_PREF_OFF 0
#define S_CH_OFF   65536
#define S_BLK_OFF  73728                 // [16][32] int
#define S_BPRE_OFF (73728 + 2048)        // [16][32] int
#define S_WCNT_OFF (73728 + 4096)        // [32][16] int
#define S_INT_OFF  (73728 + 6144)
#define SMEM_BYTES (73728 + 6144 + 128)
// s_int: [16] active, [17] start, [18] cut A, [19] cut B

__global__ void __launch_bounds__(1024) assign_kernel(float* __restrict__ out) {
    extern __shared__ unsigned char smem[];
    u64*      s_pref = (u64*)(smem + S_PREF_OFF);
    unsigned* s_ch   = (unsigned*)(smem + S_CH_OFF);   // 2048 words
    int*      s_blk  = (int*)(smem + S_BLK_OFF);
    int*      s_bpre = (int*)(smem + S_BPRE_OFF);
    int*      s_wcnt = (int*)(smem + S_WCNT_OFF);
    int*      s_int  = (int*)(smem + S_INT_OFF);

    const int tid  = threadIdx.x;
    const int lane = tid & 31;
    const int wid  = tid >> 5;
    const unsigned ltm = (1u << lane) - 1u;

    for (int i = tid; i < NT; i += 1024) s_pref[i] = g_prefs[i];
    if (tid == 0) { s_int[16] = 0xFFFF; s_int[17] = 0; s_int[18] = CINF; s_int[19] = CINF; }
    __syncthreads();

    // ---- build: warp wid counts+writes its 256-token block ----
    {
        u64 c0 = 0, c1 = 0, c2 = 0, c3 = 0;
#pragma unroll
        for (int i = 0; i < 2; ++i) {
            const int w = wid * 64 + i * 32 + lane;
            unsigned word = 0;
#pragma unroll
            for (int bb = 0; bb < 4; ++bb) {
                const int c = (int)(s_pref[w * 4 + bb] & 15);
                word |= (unsigned)c << (bb * 8);
                const u64 inc = 1ull << ((c & 3) << 4);
                if      ((c >> 2) == 0) c0 += inc;
                else if ((c >> 2) == 1) c1 += inc;
                else if ((c >> 2) == 2) c2 += inc;
                else                    c3 += inc;
            }
            s_ch[w] = word;
        }
#pragma unroll
        for (int o = 16; o; o >>= 1) {
            c0 += __shfl_xor_sync(FULLM, c0, o);
            c1 += __shfl_xor_sync(FULLM, c1, o);
            c2 += __shfl_xor_sync(FULLM, c2, o);
            c3 += __shfl_xor_sync(FULLM, c3, o);
        }
        if (lane < NE) {
            const u64 sel = (lane >> 2) == 0 ? c0 : (lane >> 2) == 1 ? c1
                          : (lane >> 2) == 2 ? c2 : c3;
            s_blk[lane * 32 + wid] = (int)((sel >> ((lane & 3) << 4)) & 0xFFFF);
        }
    }
    __syncthreads();

    // ---------------- phase loop ----------------
    for (int phase = 0; phase < NE; ++phase) {
        const int s = s_int[17];
        if (s >= NT) break;
        const int active  = s_int[16];
        const int cutslot = 18 + (phase & 1);

        // ---- step 2: warp e finds expert e's saturation position ----
        if (wid < NE && ((active >> wid) & 1)) {
            const int e = wid;
            const unsigned splat = (unsigned)e * 0x01010101u;
            const int pb   = s >> 8;
            const int ws   = s >> 2;
            const int we_  = (pb + 1) * 64;
            const unsigned mfirst = 0xFFFFFFFFu << ((s & 3) * 8);

            // live part of the partial block
            const int i0 = ws + lane * 2;
            unsigned cm0 = 0, cm1 = 0;
            if (i0 < we_) {
                cm0 = __vcmpeq4(s_ch[i0], splat);
                if (i0 == ws) cm0 &= mfirst;
            }
            if (i0 + 1 < we_) cm1 = __vcmpeq4(s_ch[i0 + 1], splat);
            const int lcnt = (__popc(cm0) + __popc(cm1)) >> 3;
            int linc = lcnt;
#pragma unroll
            for (int o = 1; o < 32; o <<= 1) {
                const int u = __shfl_up_sync(FULLM, linc, o);
                if (lane >= o) linc += u;
            }
            const int ptotal = __shfl_sync(FULLM, linc, 31);

            // block counts: full total + masked prefix
            const int bfull = s_blk[e * 32 + lane];
            int tot = bfull;
#pragma unroll
            for (int o = 16; o; o >>= 1) tot += __shfl_xor_sync(FULLM, tot, o);
            const int bval = (lane > pb) ? bfull : 0;
            int binc = bval;
#pragma unroll
            for (int o = 1; o < 32; o <<= 1) {
                const int u = __shfl_up_sync(FULLM, binc, o);
                if (lane >= o) binc += u;
            }
            const int btotal = __shfl_sync(FULLM, binc, 31);

            const int live = ptotal + btotal;
            const int need = CAP - (tot - live);    // remaining capacity

            if (live >= need) {
                if (ptotal >= need) {
                    const unsigned bal = __ballot_sync(FULLM, linc >= need);
                    const int cl = __ffs(bal) - 1;
                    if (lane == cl) {
                        int rem = need - (linc - lcnt);
                        int pos = -1;
#pragma unroll
                        for (int bb = 0; bb < 4 && pos < 0; ++bb)
                            if ((cm0 >> (bb * 8)) & 1u && --rem == 0) pos = i0 * 4 + bb;
#pragma unroll
                        for (int bb = 0; bb < 4 && pos < 0; ++bb)
                            if ((cm1 >> (bb * 8)) & 1u && --rem == 0) pos = (i0 + 1) * 4 + bb;
                        atomicMin(&s_int[cutslot], (pos << 4) | e);
                    }
                } else {
                    const int rem2 = need - ptotal;
                    const unsigned bal = __ballot_sync(FULLM, binc >= rem2);
                    const int kc   = __ffs(bal) - 1;
                    const int excl = __shfl_sync(FULLM, binc - bval, kc);
                    const int rem3 = rem2 - excl;
                    const int j0 = kc * 64 + lane * 2;
                    const unsigned d0 = __vcmpeq4(s_ch[j0], splat);
                    const unsigned d1 = __vcmpeq4(s_ch[j0 + 1], splat);
                    const int lc = (__popc(d0) + __popc(d1)) >> 3;
                    int li = lc;
#pragma unroll
                    for (int o = 1; o < 32; o <<= 1) {
                        const int u = __shfl_up_sync(FULLM, li, o);
                        if (lane >= o) li += u;
                    }
                    const unsigned bal2 = __ballot_sync(FULLM, li >= rem3);
                    const int cl2 = __ffs(bal2) - 1;
                    if (lane == cl2) {
                        int rem = rem3 - (li - lc);
                        int pos = -1;
#pragma unroll
                        for (int bb = 0; bb < 4 && pos < 0; ++bb)
                            if ((d0 >> (bb * 8)) & 1u && --rem == 0) pos = j0 * 4 + bb;
#pragma unroll
                        for (int bb = 0; bb < 4 && pos < 0; ++bb)
                            if ((d1 >> (bb * 8)) & 1u && --rem == 0) pos = (j0 + 1) * 4 + bb;
                        atomicMin(&s_int[cutslot], (pos << 4) | e);
                    }
                }
            }
        }
        __syncthreads();                               // B1: cut final

        const int mv = s_int[cutslot];
        if (mv == CINF) {                              // safety; unreachable
            if (tid == 0) s_int[17] = NT;
            __syncthreads();
            continue;
        }
        const int pstar = mv >> 4, es = mv & 15;
        const int nactive = active & ~(1 << es);

        if (tid == 0) {                                // state update
            s_int[16] = nactive;
            s_int[17] = pstar + 1;
            s_int[cutslot] = CINF;
        }
        {                                              // choice rewrite for es
            const int sn = pstar + 1;
            const int ws = sn >> 2;
            const unsigned splat = (unsigned)es * 0x01010101u;
            const unsigned mfirst = 0xFFFFFFFFu << ((sn & 3) * 8);
            for (int w = ws + tid; w < 2048; w += 1024) {
                unsigned word = s_ch[w];
                unsigned m = __vcmpeq4(word, splat);
                if (w == ws) m &= mfirst;
                if (m) {
                    const int blk = w >> 6;
                    int moved = 0;
                    do {
                        const int bb = (__ffs(m) - 1) >> 3;
                        m &= ~(0xFFu << (bb * 8));
                        u64 p = s_pref[w * 4 + bb];
                        int c = (int)(p & 15);
                        while (!((nactive >> c) & 1)) { p >>= 4; c = (int)(p & 15); }
                        word = (word & ~(0xFFu << (bb * 8))) | ((unsigned)c << (bb * 8));
                        atomicAdd(&s_blk[c * 32 + blk], 1);
                        ++moved;
                    } while (m);
                    atomicAdd(&s_blk[es * 32 + blk], -moved);
                    s_ch[w] = word;
                }
            }
        }
        __syncthreads();                               // B2: phase done
    }

    // ---------------- epilogue: rank via block prefixes + match_any ----------------
    if (wid < NE) {                 // warp e: exclusive prefix of its block counts
        const int v = s_blk[wid * 32 + lane];
        int inc = v;
#pragma unroll
        for (int o = 1; o < 32; o <<= 1) {
            const int u = __shfl_up_sync(FULLM, inc, o);
            if (lane >= o) inc += u;
        }
        s_bpre[wid * 32 + lane] = wid * CAP + inc - v;
    }
    if (lane < NE) s_wcnt[wid * 16 + lane] = 0;
    __syncthreads();

    {
        const int base = wid * 256;
#pragma unroll
        for (int j = 0; j < 8; ++j) {
            const int t = base + j * 32 + lane;
            const int e = (int)((s_ch[t >> 2] >> ((t & 3) * 8)) & 0xFFu);
            const unsigned mask = __match_any_sync(FULLM, e);
            const int leader = __ffs(mask) - 1;
            int old = 0;
            if (lane == leader) old = atomicAdd(&s_wcnt[wid * 16 + e], __popc(mask));
            old = __shfl_sync(FULLM, old, leader);
            const int rank = s_bpre[e * 32 + wid] + old + __popc(mask & ltm);
            out[rank] = (float)t;
            out[NT + t] = g_probsT[e * NT + t];
        }
    }
}

// =====================================================================
extern "C" void kernel_launch(void* const* d_in, const int* in_sizes, int n_in,
                              void* d_out, int out_size) {
    const float* f = (const float*)d_in[0];   // features [8192, 2048] f32
    const float* W = (const float*)d_in[1];   // gate weight [16, 2048] f32
    const float* b = (const float*)d_in[2];   // bias [16] f32
    float* out = (float*)d_out;               // [8192] sort_by_expert ++ [8192] gathered

    gemv_kernel<<<NT / 16, 128>>>(f, W, b);

    cudaFuncSetAttribute(assign_kernel,
                         cudaFuncAttributeMaxDynamicSharedMemorySize, SMEM_BYTES);
    assign_kernel<<<1, 1024, SMEM_BYTES>>>(out);
}

// round 8
// speedup vs baseline: 1.1724x; 1.0034x over previous
#include <cuda_runtime.h>

#define NT 8192
#define ND 2048
#define NE 16
#define CAP 512
#define FULLM 0xFFFFFFFFu
#define CINF 0x7FFFFFFF

typedef unsigned long long u64;

__device__ float g_probsT[NE * NT];  // softmax probs, transposed [e][t]
__device__ u64   g_prefs[NT];        // packed expert-preference order (16 nibbles)

__device__ __forceinline__ u64 ffma2(u64 a, u64 b, u64 c) {
    u64 d;
    asm("fma.rn.f32x2 %0, %1, %2, %3;" : "=l"(d) : "l"(a), "l"(b), "l"(c));
    return d;
}

// =====================================================================
// Kernel 1: GEMV + softmax + preference packing (unchanged)
// =====================================================================
__global__ void __launch_bounds__(128) gemv_kernel(const float* __restrict__ f,
                                                   const float* __restrict__ W,
                                                   const float* __restrict__ b) {
    const int lane = threadIdx.x & 31;
    const int wid  = threadIdx.x >> 5;
    const int t0   = (blockIdx.x * 4 + wid) * 4;

    const ulonglong2* F  = reinterpret_cast<const ulonglong2*>(f + (size_t)t0 * ND);
    const ulonglong2* Wv = reinterpret_cast<const ulonglong2*>(W);

    u64 acc[4][NE];
#pragma unroll
    for (int t = 0; t < 4; ++t)
#pragma unroll
        for (int e = 0; e < NE; ++e) acc[t][e] = 0ull;

#pragma unroll 2
    for (int i = 0; i < 16; ++i) {
        const int k = i * 32 + lane;
        const ulonglong2 a0 = F[k];
        const ulonglong2 a1 = F[k + 512];
        const ulonglong2 a2 = F[k + 1024];
        const ulonglong2 a3 = F[k + 1536];
#pragma unroll
        for (int e = 0; e < NE; ++e) {
            const ulonglong2 w = Wv[e * 512 + k];
            acc[0][e] = ffma2(a0.x, w.x, acc[0][e]);
            acc[0][e] = ffma2(a0.y, w.y, acc[0][e]);
            acc[1][e] = ffma2(a1.x, w.x, acc[1][e]);
            acc[1][e] = ffma2(a1.y, w.y, acc[1][e]);
            acc[2][e] = ffma2(a2.x, w.x, acc[2][e]);
            acc[2][e] = ffma2(a2.y, w.y, acc[2][e]);
            acc[3][e] = ffma2(a3.x, w.x, acc[3][e]);
            acc[3][e] = ffma2(a3.y, w.y, acc[3][e]);
        }
    }

    float aff[NE];
#pragma unroll
    for (int t = 0; t < 4; ++t) {
#pragma unroll
        for (int e = 0; e < NE; ++e) {
            float sv = __uint_as_float((unsigned)acc[t][e]) +
                       __uint_as_float((unsigned)(acc[t][e] >> 32));
#pragma unroll
            for (int o = 16; o; o >>= 1) sv += __shfl_xor_sync(FULLM, sv, o);
            if (lane == t) aff[e] = sv;
        }
    }

    if (lane < 4) {
        const int t = t0 + lane;
#pragma unroll
        for (int e = 0; e < NE; ++e) aff[e] += __ldg(b + e);

        float m = aff[0];
#pragma unroll
        for (int e = 1; e < NE; ++e) m = fmaxf(m, aff[e]);
        float p[NE]; float s = 0.f;
#pragma unroll
        for (int e = 0; e < NE; ++e) { p[e] = expf(aff[e] - m); s += p[e]; }
        const float inv = 1.f / s;
#pragma unroll
        for (int e = 0; e < NE; ++e) g_probsT[e * NT + t] = p[e] * inv;

        u64 key[NE];
#pragma unroll
        for (int e = 0; e < NE; ++e) {
            unsigned u = __float_as_uint(aff[e]);
            u = (u & 0x80000000u) ? ~u : (u | 0x80000000u);
            key[e] = (1ull << 40) | ((u64)u << 4) | (u64)(NE - 1 - e);
        }
        unsigned used = 0;
        u64 pref = 0;
#pragma unroll
        for (int i = 0; i < NE; ++i) {
            int best = 0; u64 bk = 0;
#pragma unroll
            for (int e = 0; e < NE; ++e) {
                const bool take = !((used >> e) & 1u) && key[e] > bk;
                bk   = take ? key[e] : bk;
                best = take ? e : best;
            }
            used |= 1u << best;
            pref |= ((u64)best) << (4 * i);
        }
        g_prefs[t] = pref;
    }
}

// =====================================================================
// Kernel 2: phased balanced assignment v7 — short dependency chains.
// =====================================================================
#define S_PREF_OFF 0
#define S_CH_OFF   65536
#define S_BLK_OFF  73728                 // [16][32] int
#define S_BPRE_OFF (73728 + 2048)        // [16][32] int
#define S_WCNT_OFF (73728 + 4096)        // [32][16] int
#define S_INT_OFF  (73728 + 6144)
#define SMEM_BYTES (73728 + 6144 + 128)
// s_int: [16] active, [17] start, [18] cut A, [19] cut B

__global__ void __launch_bounds__(1024) assign_kernel(float* __restrict__ out) {
    extern __shared__ unsigned char smem[];
    u64*      s_pref = (u64*)(smem + S_PREF_OFF);
    unsigned* s_ch   = (unsigned*)(smem + S_CH_OFF);   // 2048 words
    int*      s_blk  = (int*)(smem + S_BLK_OFF);
    int*      s_bpre = (int*)(smem + S_BPRE_OFF);
    int*      s_wcnt = (int*)(smem + S_WCNT_OFF);
    int*      s_int  = (int*)(smem + S_INT_OFF);

    const int tid  = threadIdx.x;
    const int lane = tid & 31;
    const int wid  = tid >> 5;
    const unsigned ltm = (1u << lane) - 1u;

    for (int i = tid; i < NT; i += 1024) s_pref[i] = g_prefs[i];
    if (tid == 0) { s_int[16] = 0xFFFF; s_int[17] = 0; s_int[18] = CINF; s_int[19] = CINF; }
    __syncthreads();

    // ---- build: warp wid counts+writes its 256-token block ----
    {
        u64 c0 = 0, c1 = 0, c2 = 0, c3 = 0;
#pragma unroll
        for (int i = 0; i < 2; ++i) {
            const int w = wid * 64 + i * 32 + lane;
            unsigned word = 0;
#pragma unroll
            for (int bb = 0; bb < 4; ++bb) {
                const int c = (int)(s_pref[w * 4 + bb] & 15);
                word |= (unsigned)c << (bb * 8);
                const u64 inc = 1ull << ((c & 3) << 4);
                if      ((c >> 2) == 0) c0 += inc;
                else if ((c >> 2) == 1) c1 += inc;
                else if ((c >> 2) == 2) c2 += inc;
                else                    c3 += inc;
            }
            s_ch[w] = word;
        }
#pragma unroll
        for (int o = 16; o; o >>= 1) {
            c0 += __shfl_xor_sync(FULLM, c0, o);
            c1 += __shfl_xor_sync(FULLM, c1, o);
            c2 += __shfl_xor_sync(FULLM, c2, o);
            c3 += __shfl_xor_sync(FULLM, c3, o);
        }
        if (lane < NE) {
            const u64 sel = (lane >> 2) == 0 ? c0 : (lane >> 2) == 1 ? c1
                          : (lane >> 2) == 2 ? c2 : c3;
            s_blk[lane * 32 + wid] = (int)((sel >> ((lane & 3) << 4)) & 0xFFFF);
        }
    }
    __syncthreads();

    // ---------------- phase loop ----------------
    for (int phase = 0; phase < NE; ++phase) {
        const int s = s_int[17];
        const int active  = s_int[16];
        const int cutslot = 18 + (phase & 1);

        // ---- step 2: warp e finds expert e's saturation position ----
        if (wid < NE && ((active >> wid) & 1)) {
            const int e = wid;
            const unsigned splat = (unsigned)e * 0x01010101u;
            const int pb   = s >> 8;
            const int ws   = s >> 2;
            const int we_  = (pb + 1) * 64;
            const unsigned mfirst = 0xFFFFFFFFu << ((s & 3) * 8);

            // live part of the partial block (count only; no prefix chain)
            const int i0 = ws + lane * 2;
            unsigned cm0 = 0, cm1 = 0;
            if (i0 < we_) {
                cm0 = __vcmpeq4(s_ch[i0], splat);
                if (i0 == ws) cm0 &= mfirst;
            }
            if (i0 + 1 < we_) cm1 = __vcmpeq4(s_ch[i0 + 1], splat);
            const int lcnt = (__popc(cm0) + __popc(cm1)) >> 3;
            const int ptotal = (int)__reduce_add_sync(FULLM, (unsigned)lcnt);

            // single inclusive scan of raw block counts
            const int bfull = s_blk[e * 32 + lane];
            int incl = bfull;
#pragma unroll
            for (int o = 1; o < 32; o <<= 1) {
                const int u = __shfl_up_sync(FULLM, incl, o);
                if (lane >= o) incl += u;
            }
            const int tot     = __shfl_sync(FULLM, incl, 31);
            const int pref_pb = __shfl_sync(FULLM, incl, pb);   // blocks 0..pb
            const int need    = CAP - (pref_pb - ptotal);        // CAP - finalized
            const int live    = tot - pref_pb + ptotal;

            if (live >= need) {
                if (ptotal >= need) {
                    // rare: crossing inside the partial block — do prefix now
                    int linc = lcnt;
#pragma unroll
                    for (int o = 1; o < 32; o <<= 1) {
                        const int u = __shfl_up_sync(FULLM, linc, o);
                        if (lane >= o) linc += u;
                    }
                    const unsigned bal = __ballot_sync(FULLM, linc >= need);
                    const int cl = __ffs(bal) - 1;
                    if (lane == cl) {
                        int rem = need - (linc - lcnt);
                        int pos = -1;
#pragma unroll
                        for (int bb = 0; bb < 4 && pos < 0; ++bb)
                            if ((cm0 >> (bb * 8)) & 1u && --rem == 0) pos = i0 * 4 + bb;
#pragma unroll
                        for (int bb = 0; bb < 4 && pos < 0; ++bb)
                            if ((cm1 >> (bb * 8)) & 1u && --rem == 0) pos = (i0 + 1) * 4 + bb;
                        atomicMin(&s_int[cutslot], (pos << 4) | e);
                    }
                } else {
                    const int rem2 = need - ptotal;
                    const int minc = incl - pref_pb;             // masked prefix, lanes > pb
                    const unsigned bal = __ballot_sync(FULLM, lane > pb && minc >= rem2);
                    const int kc   = __ffs(bal) - 1;             // crossing block
                    const int excl = __shfl_sync(FULLM, incl - bfull, kc) - pref_pb;
                    const int rem3 = rem2 - excl;
                    const int j0 = kc * 64 + lane * 2;
                    const unsigned d0 = __vcmpeq4(s_ch[j0], splat);
                    const unsigned d1 = __vcmpeq4(s_ch[j0 + 1], splat);
                    const int lc = (__popc(d0) + __popc(d1)) >> 3;
                    int li = lc;
#pragma unroll
                    for (int o = 1; o < 32; o <<= 1) {
                        const int u = __shfl_up_sync(FULLM, li, o);
                        if (lane >= o) li += u;
                    }
                    const unsigned bal2 = __ballot_sync(FULLM, li >= rem3);
                    const int cl2 = __ffs(bal2) - 1;
                    if (lane == cl2) {
                        int rem = rem3 - (li - lc);
                        int pos = -1;
#pragma unroll
                        for (int bb = 0; bb < 4 && pos < 0; ++bb)
                            if ((d0 >> (bb * 8)) & 1u && --rem == 0) pos = j0 * 4 + bb;
#pragma unroll
                        for (int bb = 0; bb < 4 && pos < 0; ++bb)
                            if ((d1 >> (bb * 8)) & 1u && --rem == 0) pos = (j0 + 1) * 4 + bb;
                        atomicMin(&s_int[cutslot], (pos << 4) | e);
                    }
                }
            }
        }
        __syncthreads();                               // B1: cut final

        const int mv = s_int[cutslot];
        if (mv == CINF) {                              // safety; unreachable
            if (tid == 0) s_int[17] = NT;
            __syncthreads();
            continue;
        }
        const int pstar = mv >> 4, es = mv & 15;
        const int nactive = active & ~(1 << es);

        if (tid == 0) {                                // state update
            s_int[16] = nactive;
            s_int[17] = pstar + 1;
            s_int[cutslot] = CINF;
        }
        {                                              // choice rewrite for es
            const int sn = pstar + 1;
            const int ws = sn >> 2;
            const unsigned splat = (unsigned)es * 0x01010101u;
            const unsigned mfirst = 0xFFFFFFFFu << ((sn & 3) * 8);
            for (int w = ws + tid; w < 2048; w += 1024) {
                unsigned word = s_ch[w];
                unsigned m = __vcmpeq4(word, splat);
                if (w == ws) m &= mfirst;
                if (m) {
                    const int blk = w >> 6;
                    int moved = 0;
                    do {
                        const int bb = (__ffs(m) - 1) >> 3;
                        m &= ~(0xFFu << (bb * 8));
                        u64 p = s_pref[w * 4 + bb];
                        int c = (int)(p & 15);
                        while (!((nactive >> c) & 1)) { p >>= 4; c = (int)(p & 15); }
                        word = (word & ~(0xFFu << (bb * 8))) | ((unsigned)c << (bb * 8));
                        atomicAdd(&s_blk[c * 32 + blk], 1);
                        ++moved;
                    } while (m);
                    atomicAdd(&s_blk[es * 32 + blk], -moved);
                    s_ch[w] = word;
                }
            }
        }
        __syncthreads();                               // B2: phase done
    }

    // ---------------- epilogue: rank via block prefixes + match_any ----------------
    if (wid < NE) {                 // warp e: exclusive prefix of its block counts
        const int v = s_blk[wid * 32 + lane];
        int inc = v;
#pragma unroll
        for (int o = 1; o < 32; o <<= 1) {
            const int u = __shfl_up_sync(FULLM, inc, o);
            if (lane >= o) inc += u;
        }
        s_bpre[wid * 32 + lane] = wid * CAP + inc - v;
    }
    if (lane < NE) s_wcnt[wid * 16 + lane] = 0;
    __syncthreads();

    {
        const int base = wid * 256;
#pragma unroll
        for (int j = 0; j < 8; ++j) {
            const int t = base + j * 32 + lane;
            const int e = (int)((s_ch[t >> 2] >> ((t & 3) * 8)) & 0xFFu);
            const unsigned mask = __match_any_sync(FULLM, e);
            const int leader = __ffs(mask) - 1;
            int old = 0;
            if (lane == leader) old = atomicAdd(&s_wcnt[wid * 16 + e], __popc(mask));
            old = __shfl_sync(FULLM, old, leader);
            const int rank = s_bpre[e * 32 + wid] + old + __popc(mask & ltm);
            out[rank] = (float)t;
            out[NT + t] = g_probsT[e * NT + t];
        }
    }
}

// =====================================================================
extern "C" void kernel_launch(void* const* d_in, const int* in_sizes, int n_in,
                              void* d_out, int out_size) {
    const float* f = (const float*)d_in[0];   // features [8192, 2048] f32
    const float* W = (const float*)d_in[1];   // gate weight [16, 2048] f32
    const float* b = (const float*)d_in[2];   // bias [16] f32
    float* out = (float*)d_out;               // [8192] sort_by_expert ++ [8192] gathered

    gemv_kernel<<<NT / 16, 128>>>(f, W, b);

    cudaFuncSetAttribute(assign_kernel,
                         cudaFuncAttributeMaxDynamicSharedMemorySize, SMEM_BYTES);
    assign_kernel<<<1, 1024, SMEM_BYTES>>>(out);
}